// round 2
// baseline (speedup 1.0000x reference)
#include <cuda_runtime.h>

#define GRID_SZ 256
#define NVOX (GRID_SZ * GRID_SZ * GRID_SZ)

// 64 MB difference volume (pred splat adds +w, gt splat adds -w).
// __device__ globals are zero-initialized at module load; the reduce kernel
// re-zeros every voxel it reads, preserving the invariant across graph replays.
__device__ float g_vol[NVOX];

__device__ __forceinline__ void splat(float px, float py, float pz, float s) {
    // Match reference arithmetic exactly: p = ((g+1)*size - 1) * 0.5
    float x = ((px + 1.0f) * 256.0f - 1.0f) * 0.5f;
    float y = ((py + 1.0f) * 256.0f - 1.0f) * 0.5f;
    float z = ((pz + 1.0f) * 256.0f - 1.0f) * 0.5f;
    float x0f = floorf(x), y0f = floorf(y), z0f = floorf(z);
    int x0 = (int)x0f, y0 = (int)y0f, z0 = (int)z0f;
    float fx = x - x0f, fy = y - y0f, fz = z - z0f;
    float wx0 = 1.0f - fx, wx1 = fx;
    float wy0 = 1.0f - fy, wy1 = fy;
    float wz0 = 1.0f - fz, wz1 = fz;

    bool vx0 = ((unsigned)x0 < GRID_SZ);
    bool vx1 = ((unsigned)(x0 + 1) < GRID_SZ);

#pragma unroll
    for (int dz = 0; dz < 2; dz++) {
        int zi = z0 + dz;
        if ((unsigned)zi >= GRID_SZ) continue;
        float wz = (dz ? wz1 : wz0) * s;
#pragma unroll
        for (int dy = 0; dy < 2; dy++) {
            int yi = y0 + dy;
            if ((unsigned)yi >= GRID_SZ) continue;
            float wzy = wz * (dy ? wy1 : wy0);
            int base = (zi * GRID_SZ + yi) * GRID_SZ;
            if (vx0) atomicAdd(&g_vol[base + x0],     wzy * wx0);
            if (vx1) atomicAdd(&g_vol[base + x0 + 1], wzy * wx1);
        }
    }
}

__global__ void scatter_kernel(const float* __restrict__ pred,
                               const float* __restrict__ gt,
                               const float* __restrict__ coords,
                               float* __restrict__ out, int n) {
    int i = blockIdx.x * blockDim.x + threadIdx.x;
    if (i == 0) out[0] = 0.0f;  // reduce kernel runs after us in stream order
    if (i >= n) return;

    float cx = coords[3 * i + 0];
    float cy = coords[3 * i + 1];
    float cz = coords[3 * i + 2];

    splat(cx + pred[3 * i + 0], cy + pred[3 * i + 1], cz + pred[3 * i + 2],  1.0f);
    splat(cx + gt[3 * i + 0],   cy + gt[3 * i + 1],   cz + gt[3 * i + 2],  -1.0f);
}

__device__ __forceinline__ float huber(float d) {
    float ad = fabsf(d);
    return (ad <= 1.0f) ? 0.5f * d * d : (ad - 0.5f);
}

__global__ void huber_reduce_kernel(float* __restrict__ out) {
    float4* v4 = reinterpret_cast<float4*>(g_vol);
    const int n4 = NVOX / 4;
    const float4 zero4 = make_float4(0.f, 0.f, 0.f, 0.f);

    float acc = 0.0f;
    for (int i = blockIdx.x * blockDim.x + threadIdx.x; i < n4;
         i += gridDim.x * blockDim.x) {
        float4 v = v4[i];
        v4[i] = zero4;  // re-zero for next graph replay
        acc += huber(v.x) + huber(v.y) + huber(v.z) + huber(v.w);
    }

    // warp reduce
#pragma unroll
    for (int o = 16; o; o >>= 1) acc += __shfl_xor_sync(0xFFFFFFFFu, acc, o);

    __shared__ float sm[32];
    int lane = threadIdx.x & 31;
    int wid = threadIdx.x >> 5;
    if (lane == 0) sm[wid] = acc;
    __syncthreads();
    if (wid == 0) {
        int nw = blockDim.x >> 5;
        float v = (lane < nw) ? sm[lane] : 0.0f;
#pragma unroll
        for (int o = 16; o; o >>= 1) v += __shfl_xor_sync(0xFFFFFFFFu, v, o);
        if (lane == 0) atomicAdd(out, v);
    }
}

extern "C" void kernel_launch(void* const* d_in, const int* in_sizes, int n_in,
                              void* d_out, int out_size) {
    const float* pred   = (const float*)d_in[0];
    const float* gt     = (const float*)d_in[1];
    const float* coords = (const float*)d_in[2];
    float* out = (float*)d_out;

    int n = in_sizes[0] / 3;  // N_POINTS

    int threads = 256;
    int blocks = (n + threads - 1) / threads;
    scatter_kernel<<<blocks, threads>>>(pred, gt, coords, out, n);

    // 16.7M voxels / 4 per thread-iter; grid-stride
    huber_reduce_kernel<<<2048, 256>>>(out);
}

// round 3
// speedup vs baseline: 1.3500x; 1.3500x over previous
#include <cuda_runtime.h>

#define GRID_SZ 256
#define NVOX (GRID_SZ * GRID_SZ * GRID_SZ)

// 64 MB difference volume (pred splat adds +w, gt splat adds -w).
// Zero-initialized at module load; the reduce kernel re-zeros every voxel it
// reads, preserving the invariant across graph replays.
__device__ float g_vol[NVOX];

__device__ __forceinline__ void splat(float px, float py, float pz, float s) {
    // Match reference arithmetic exactly: p = ((g+1)*size - 1) * 0.5
    float x = ((px + 1.0f) * 256.0f - 1.0f) * 0.5f;
    float y = ((py + 1.0f) * 256.0f - 1.0f) * 0.5f;
    float z = ((pz + 1.0f) * 256.0f - 1.0f) * 0.5f;
    float x0f = floorf(x), y0f = floorf(y), z0f = floorf(z);
    int x0 = (int)x0f, y0 = (int)y0f, z0 = (int)z0f;
    float fx = x - x0f, fy = y - y0f, fz = z - z0f;
    float wx0 = 1.0f - fx, wx1 = fx;
    float wy0 = 1.0f - fy, wy1 = fy;
    float wz0 = 1.0f - fz, wz1 = fz;

    bool vx0 = ((unsigned)x0 < GRID_SZ);
    bool vx1 = ((unsigned)(x0 + 1) < GRID_SZ);

#pragma unroll
    for (int dz = 0; dz < 2; dz++) {
        int zi = z0 + dz;
        if ((unsigned)zi >= GRID_SZ) continue;
        float wz = (dz ? wz1 : wz0) * s;
#pragma unroll
        for (int dy = 0; dy < 2; dy++) {
            int yi = y0 + dy;
            if ((unsigned)yi >= GRID_SZ) continue;
            float wzy = wz * (dy ? wy1 : wy0);
            int base = (zi * GRID_SZ + yi) * GRID_SZ;
            if (vx0) atomicAdd(&g_vol[base + x0],     wzy * wx0);
            if (vx1) atomicAdd(&g_vol[base + x0 + 1], wzy * wx1);
        }
    }
}

__global__ void scatter_kernel(const float* __restrict__ pred,
                               const float* __restrict__ gt,
                               const float* __restrict__ coords,
                               float* __restrict__ out, int n) {
    int i = blockIdx.x * blockDim.x + threadIdx.x;
    if (i == 0) out[0] = 0.0f;  // reduce kernel runs after us in stream order
    if (i >= n) return;

    // Streaming (evict-first) loads: keep L2 capacity for the volume.
    float cx = __ldcs(&coords[3 * i + 0]);
    float cy = __ldcs(&coords[3 * i + 1]);
    float cz = __ldcs(&coords[3 * i + 2]);
    float p0 = __ldcs(&pred[3 * i + 0]);
    float p1 = __ldcs(&pred[3 * i + 1]);
    float p2 = __ldcs(&pred[3 * i + 2]);
    float g0 = __ldcs(&gt[3 * i + 0]);
    float g1 = __ldcs(&gt[3 * i + 1]);
    float g2 = __ldcs(&gt[3 * i + 2]);

    splat(cx + p0, cy + p1, cz + p2,  1.0f);
    splat(cx + g0, cy + g1, cz + g2, -1.0f);
}

__device__ __forceinline__ float huber(float d) {
    float ad = fabsf(d);
    return (ad <= 1.0f) ? 0.5f * d * d : (ad - 0.5f);
}

__device__ __forceinline__ float huber4(float4 v) {
    return huber(v.x) + huber(v.y) + huber(v.z) + huber(v.w);
}

// 4096 blocks x 256 threads; each thread handles exactly 4 float4s at stride
// TOTAL_THREADS (fully coalesced, 4 independent loads in flight = MLP 4).
// NVOX/4 = 4194304 = 4 * 1048576 exactly -> no bounds checks.
#define RED_BLOCKS 4096
#define RED_THREADS 256
#define RED_TOTAL (RED_BLOCKS * RED_THREADS)

__global__ void __launch_bounds__(RED_THREADS)
huber_reduce_kernel(float* __restrict__ out) {
    float4* v4 = reinterpret_cast<float4*>(g_vol);
    const int tid = blockIdx.x * RED_THREADS + threadIdx.x;
    const float4 zero4 = make_float4(0.f, 0.f, 0.f, 0.f);

    // Front-batched independent loads
    float4 a0 = v4[tid + 0 * RED_TOTAL];
    float4 a1 = v4[tid + 1 * RED_TOTAL];
    float4 a2 = v4[tid + 2 * RED_TOTAL];
    float4 a3 = v4[tid + 3 * RED_TOTAL];

    // Re-zero for the next graph replay
    v4[tid + 0 * RED_TOTAL] = zero4;
    v4[tid + 1 * RED_TOTAL] = zero4;
    v4[tid + 2 * RED_TOTAL] = zero4;
    v4[tid + 3 * RED_TOTAL] = zero4;

    float acc = huber4(a0) + huber4(a1) + huber4(a2) + huber4(a3);

    // warp reduce
#pragma unroll
    for (int o = 16; o; o >>= 1) acc += __shfl_xor_sync(0xFFFFFFFFu, acc, o);

    __shared__ float sm[RED_THREADS / 32];
    int lane = threadIdx.x & 31;
    int wid = threadIdx.x >> 5;
    if (lane == 0) sm[wid] = acc;
    __syncthreads();
    if (wid == 0) {
        float v = (lane < (RED_THREADS / 32)) ? sm[lane] : 0.0f;
#pragma unroll
        for (int o = 16; o; o >>= 1) v += __shfl_xor_sync(0xFFFFFFFFu, v, o);
        if (lane == 0) atomicAdd(out, v);
    }
}

extern "C" void kernel_launch(void* const* d_in, const int* in_sizes, int n_in,
                              void* d_out, int out_size) {
    const float* pred   = (const float*)d_in[0];
    const float* gt     = (const float*)d_in[1];
    const float* coords = (const float*)d_in[2];
    float* out = (float*)d_out;

    int n = in_sizes[0] / 3;  // N_POINTS

    int threads = 256;
    int blocks = (n + threads - 1) / threads;
    scatter_kernel<<<blocks, threads>>>(pred, gt, coords, out, n);

    huber_reduce_kernel<<<RED_BLOCKS, RED_THREADS>>>(out);
}

// round 4
// speedup vs baseline: 2.1307x; 1.5783x over previous
#include <cuda_runtime.h>

#define GRID_SZ 256
#define NVOX (GRID_SZ * GRID_SZ * GRID_SZ)

// 64 MB difference volume (pred splat adds +w, gt splat adds -w).
// Zero-initialized at module load; the reduce kernel re-zeros every voxel it
// reads, preserving the invariant across graph replays.
__device__ __align__(16) float g_vol[NVOX];

__device__ __forceinline__ void red_add_f32(float* addr, float a) {
    asm volatile("red.global.add.f32 [%0], %1;" :: "l"(addr), "f"(a) : "memory");
}

__device__ __forceinline__ void red_add_v4(float* addr, float a, float b,
                                           float c, float d) {
    asm volatile("red.global.add.v4.f32 [%0], {%1, %2, %3, %4};"
                 :: "l"(addr), "f"(a), "f"(b), "f"(c), "f"(d) : "memory");
}

// Add w0 at row[x0], w1 at row[x0+1] using one vector RED when the pair fits
// in an aligned 16B block (lane = x0&3 in {0,1,2}; 75% of cases).
__device__ __forceinline__ void row_pair_add(float* row, int x0,
                                             bool vx0, bool vx1,
                                             float w0, float w1) {
    if (vx0 & vx1) {
        int lane = x0 & 3;
        if (lane != 3) {
            float* base = row + (x0 & ~3);
            float v0 = (lane == 0) ? w0 : 0.0f;
            float v1 = (lane == 0) ? w1 : ((lane == 1) ? w0 : 0.0f);
            float v2 = (lane == 1) ? w1 : ((lane == 2) ? w0 : 0.0f);
            float v3 = (lane == 2) ? w1 : 0.0f;
            red_add_v4(base, v0, v1, v2, v3);
        } else {
            red_add_f32(row + x0, w0);
            red_add_f32(row + x0 + 1, w1);
        }
    } else if (vx0) {
        red_add_f32(row + x0, w0);
    } else if (vx1) {
        red_add_f32(row + x0 + 1, w1);
    }
}

__device__ __forceinline__ void splat(float px, float py, float pz, float s) {
    // Match reference arithmetic exactly: p = ((g+1)*size - 1) * 0.5
    float x = ((px + 1.0f) * 256.0f - 1.0f) * 0.5f;
    float y = ((py + 1.0f) * 256.0f - 1.0f) * 0.5f;
    float z = ((pz + 1.0f) * 256.0f - 1.0f) * 0.5f;
    float x0f = floorf(x), y0f = floorf(y), z0f = floorf(z);
    int x0 = (int)x0f, y0 = (int)y0f, z0 = (int)z0f;
    float fx = x - x0f, fy = y - y0f, fz = z - z0f;
    float wx0 = 1.0f - fx, wx1 = fx;
    float wy0 = 1.0f - fy, wy1 = fy;
    float wz0 = 1.0f - fz, wz1 = fz;

    bool vx0 = ((unsigned)x0 < GRID_SZ);
    bool vx1 = ((unsigned)(x0 + 1) < GRID_SZ);

#pragma unroll
    for (int dz = 0; dz < 2; dz++) {
        int zi = z0 + dz;
        if ((unsigned)zi >= GRID_SZ) continue;
        float wz = (dz ? wz1 : wz0) * s;
#pragma unroll
        for (int dy = 0; dy < 2; dy++) {
            int yi = y0 + dy;
            if ((unsigned)yi >= GRID_SZ) continue;
            float wzy = wz * (dy ? wy1 : wy0);
            float* row = g_vol + (zi * GRID_SZ + yi) * GRID_SZ;
            row_pair_add(row, x0, vx0, vx1, wzy * wx0, wzy * wx1);
        }
    }
}

__global__ void scatter_kernel(const float* __restrict__ pred,
                               const float* __restrict__ gt,
                               const float* __restrict__ coords,
                               float* __restrict__ out, int n) {
    int i = blockIdx.x * blockDim.x + threadIdx.x;
    if (i == 0) out[0] = 0.0f;  // reduce kernel runs after us in stream order
    if (i >= n) return;

    // Streaming (evict-first) loads: keep L2 capacity for the volume.
    float cx = __ldcs(&coords[3 * i + 0]);
    float cy = __ldcs(&coords[3 * i + 1]);
    float cz = __ldcs(&coords[3 * i + 2]);
    float p0 = __ldcs(&pred[3 * i + 0]);
    float p1 = __ldcs(&pred[3 * i + 1]);
    float p2 = __ldcs(&pred[3 * i + 2]);
    float g0 = __ldcs(&gt[3 * i + 0]);
    float g1 = __ldcs(&gt[3 * i + 1]);
    float g2 = __ldcs(&gt[3 * i + 2]);

    splat(cx + p0, cy + p1, cz + p2,  1.0f);
    splat(cx + g0, cy + g1, cz + g2, -1.0f);
}

__device__ __forceinline__ float huber(float d) {
    float ad = fabsf(d);
    return (ad <= 1.0f) ? 0.5f * d * d : (ad - 0.5f);
}

__device__ __forceinline__ float huber4(float4 v) {
    return huber(v.x) + huber(v.y) + huber(v.z) + huber(v.w);
}

// 2048 blocks x 256 threads; each thread handles exactly 8 float4s at stride
// RED_TOTAL (fully coalesced, 8 independent loads in flight = MLP 8).
// NVOX/4 = 4194304 = 8 * 524288 exactly -> no bounds checks.
#define RED_BLOCKS 2048
#define RED_THREADS 256
#define RED_TOTAL (RED_BLOCKS * RED_THREADS)
#define RED_ITERS 8

__global__ void __launch_bounds__(RED_THREADS)
huber_reduce_kernel(float* __restrict__ out) {
    float4* v4 = reinterpret_cast<float4*>(g_vol);
    const int tid = blockIdx.x * RED_THREADS + threadIdx.x;
    const float4 zero4 = make_float4(0.f, 0.f, 0.f, 0.f);

    float4 a[RED_ITERS];
#pragma unroll
    for (int k = 0; k < RED_ITERS; k++)
        a[k] = v4[tid + k * RED_TOTAL];

    // Re-zero for the next graph replay
#pragma unroll
    for (int k = 0; k < RED_ITERS; k++)
        v4[tid + k * RED_TOTAL] = zero4;

    float acc = 0.0f;
#pragma unroll
    for (int k = 0; k < RED_ITERS; k++)
        acc += huber4(a[k]);

    // warp reduce
#pragma unroll
    for (int o = 16; o; o >>= 1) acc += __shfl_xor_sync(0xFFFFFFFFu, acc, o);

    __shared__ float sm[RED_THREADS / 32];
    int lane = threadIdx.x & 31;
    int wid = threadIdx.x >> 5;
    if (lane == 0) sm[wid] = acc;
    __syncthreads();
    if (wid == 0) {
        float v = (lane < (RED_THREADS / 32)) ? sm[lane] : 0.0f;
#pragma unroll
        for (int o = 16; o; o >>= 1) v += __shfl_xor_sync(0xFFFFFFFFu, v, o);
        if (lane == 0) atomicAdd(out, v);
    }
}

extern "C" void kernel_launch(void* const* d_in, const int* in_sizes, int n_in,
                              void* d_out, int out_size) {
    const float* pred   = (const float*)d_in[0];
    const float* gt     = (const float*)d_in[1];
    const float* coords = (const float*)d_in[2];
    float* out = (float*)d_out;

    int n = in_sizes[0] / 3;  // N_POINTS

    int threads = 256;
    int blocks = (n + threads - 1) / threads;
    scatter_kernel<<<blocks, threads>>>(pred, gt, coords, out, n);

    huber_reduce_kernel<<<RED_BLOCKS, RED_THREADS>>>(out);
}